// round 2
// baseline (speedup 1.0000x reference)
#include <cuda_runtime.h>
#include <cuda_bf16.h>

#define N_NODES 100000
#define N_EDGES 3200000
#define HID 64

// ---------------- scratch (static device globals; no allocation) ----------------
__device__ int    g_is64;                    // 1 if edge_index is int64, else int32
__device__ int    g_src[N_EDGES];
__device__ int    g_dst[N_EDGES];
__device__ int    g_cnt[N_NODES];
__device__ int    g_rowptr[N_NODES + 1];
__device__ int    g_cursor[N_NODES];
__device__ int2   g_edge[N_EDGES];           // {src, bitcast(w)} bucketed by dst
__device__ float  g_a1[N_NODES];             // layer-1 scalar aggregation
__device__ float4 g_g1[N_NODES * HID / 4];   // h1 @ W2_rel      (16B aligned)
__device__ float4 g_p2[N_NODES * HID / 4];   // b2 + h1 @ W2_root (16B aligned)
__device__ float  g_s[N_NODES];              // h2 . W3_rel
__device__ float  g_t[N_NODES];              // h2 . W3_root

// ---------------- K-1: detect int64 vs int32 edge_index ----------------
// int64 node ids (< 2^31, non-negative, little-endian): every odd 32-bit word is 0.
// int32 ids in [0,100000): 1024 consecutive odd words all zero is impossible.
__global__ void k_detect(const unsigned int* __restrict__ w) {
    int t = threadIdx.x;                     // 32 threads
    unsigned int v = 0;
    for (int i = t; i < 1024; i += 32) v |= w[2 * i + 1];
    #pragma unroll
    for (int off = 16; off > 0; off >>= 1)
        v |= __shfl_down_sync(0xFFFFFFFFu, v, off);
    if (t == 0) g_is64 = (v == 0) ? 1 : 0;
}

// ---------------- K0: normalize edge_index to int32 src/dst ----------------
__global__ void k_convert(const void* __restrict__ ei_raw) {
    int e = blockIdx.x * blockDim.x + threadIdx.x;
    if (e >= N_EDGES) return;
    if (g_is64) {
        const long long* ei = (const long long*)ei_raw;
        g_src[e] = (int)ei[e];
        g_dst[e] = (int)ei[N_EDGES + e];
    } else {
        const int* ei = (const int*)ei_raw;
        g_src[e] = ei[e];
        g_dst[e] = ei[N_EDGES + e];
    }
}

// ---------------- K1: zero histogram ----------------
__global__ void k_zero() {
    int i = blockIdx.x * blockDim.x + threadIdx.x;
    if (i < N_NODES) g_cnt[i] = 0;
}

// ---------------- K2: histogram of dst ----------------
__global__ void k_hist() {
    int e = blockIdx.x * blockDim.x + threadIdx.x;
    if (e < N_EDGES) atomicAdd(&g_cnt[g_dst[e]], 1);
}

// ---------------- K3: single-block exclusive scan -> rowptr, cursor ----------------
__global__ void k_scan() {
    const int T = 1024;
    __shared__ int buf0[T];
    __shared__ int buf1[T];
    __shared__ int s_carry;
    int tid = threadIdx.x;
    if (tid == 0) s_carry = 0;
    __syncthreads();

    for (int base = 0; base < N_NODES; base += T * 4) {
        int idx = base + tid * 4;
        int v0 = (idx + 0 < N_NODES) ? g_cnt[idx + 0] : 0;
        int v1 = (idx + 1 < N_NODES) ? g_cnt[idx + 1] : 0;
        int v2 = (idx + 2 < N_NODES) ? g_cnt[idx + 2] : 0;
        int v3 = (idx + 3 < N_NODES) ? g_cnt[idx + 3] : 0;
        int tsum = v0 + v1 + v2 + v3;

        int* a = buf0;
        int* b = buf1;
        a[tid] = tsum;
        __syncthreads();
        #pragma unroll
        for (int off = 1; off < T; off <<= 1) {
            int val = a[tid];
            if (tid >= off) val += a[tid - off];
            b[tid] = val;
            __syncthreads();
            int* t_ = a; a = b; b = t_;
        }
        int incl = a[tid];
        int carry = s_carry;
        __syncthreads();

        int run = carry + incl - tsum;   // exclusive prefix
        if (idx + 0 < N_NODES) { g_rowptr[idx + 0] = run; g_cursor[idx + 0] = run; run += v0; }
        if (idx + 1 < N_NODES) { g_rowptr[idx + 1] = run; g_cursor[idx + 1] = run; run += v1; }
        if (idx + 2 < N_NODES) { g_rowptr[idx + 2] = run; g_cursor[idx + 2] = run; run += v2; }
        if (idx + 3 < N_NODES) { g_rowptr[idx + 3] = run; g_cursor[idx + 3] = run; run += v3; }

        if (tid == T - 1) s_carry = carry + incl;
        __syncthreads();
    }
    if (tid == 0) g_rowptr[N_NODES] = N_EDGES;
}

// ---------------- K4: scatter edges into dst buckets ----------------
__global__ void k_scatter(const float* __restrict__ ew) {
    int e = blockIdx.x * blockDim.x + threadIdx.x;
    if (e < N_EDGES) {
        int pos = atomicAdd(&g_cursor[g_dst[e]], 1);
        g_edge[pos] = make_int2(g_src[e], __float_as_int(ew[e]));
    }
}

// ---------------- K5: layer-1 scalar aggregation ----------------
__global__ void k_agg1(const float* __restrict__ x) {
    int i = blockIdx.x * blockDim.x + threadIdx.x;
    if (i >= N_NODES) return;
    int beg = g_rowptr[i], end = g_rowptr[i + 1];
    float acc = 0.f;
    for (int e = beg; e < end; e++) {
        int2 ed = g_edge[e];
        acc = fmaf(__int_as_float(ed.y), __ldg(&x[ed.x]), acc);
    }
    g_a1[i] = acc;
}

// ---------------- K6: per-node dense: h1 -> g1 = h1@W2_rel, p2 = b2 + h1@W2_root --------
__global__ void __launch_bounds__(256) k_dense(
    const float* __restrict__ x,
    const float* __restrict__ W1_rel, const float* __restrict__ b1,
    const float* __restrict__ W1_root,
    const float* __restrict__ W2_rel, const float* __restrict__ b2,
    const float* __restrict__ W2_root)
{
    __shared__ float sW1r[HID], sB1[HID], sW1o[HID], sB2[HID];
    __shared__ float4 sW2r[HID * HID / 4];
    __shared__ float4 sW2o[HID * HID / 4];
    int tid = threadIdx.x;
    if (tid < HID) { sW1r[tid] = W1_rel[tid]; sB1[tid] = b1[tid];
                     sW1o[tid] = W1_root[tid]; sB2[tid] = b2[tid]; }
    for (int k = tid; k < HID * HID / 4; k += 256) {
        sW2r[k] = ((const float4*)W2_rel)[k];
        sW2o[k] = ((const float4*)W2_root)[k];
    }
    __syncthreads();

    int i = blockIdx.x * 256 + tid;
    if (i >= N_NODES) return;
    float xi = x[i];
    float ai = g_a1[i];

    float4 acc[16];
    // ---- pass A: g1 = h1 @ W2_rel
    #pragma unroll
    for (int j = 0; j < 16; j++) acc[j] = make_float4(0.f, 0.f, 0.f, 0.f);
    for (int c = 0; c < HID; c++) {
        float h = fmaxf(fmaf(ai, sW1r[c], fmaf(xi, sW1o[c], sB1[c])), 0.f);
        const float4* row = &sW2r[c * (HID / 4)];
        #pragma unroll
        for (int j = 0; j < 16; j++) {
            float4 w = row[j];
            acc[j].x = fmaf(h, w.x, acc[j].x);
            acc[j].y = fmaf(h, w.y, acc[j].y);
            acc[j].z = fmaf(h, w.z, acc[j].z);
            acc[j].w = fmaf(h, w.w, acc[j].w);
        }
    }
    {
        float4* out1 = &g_g1[i * (HID / 4)];
        #pragma unroll
        for (int j = 0; j < 16; j++) out1[j] = acc[j];
    }
    // ---- pass B: p2 = b2 + h1 @ W2_root
    #pragma unroll
    for (int j = 0; j < 16; j++) acc[j] = make_float4(0.f, 0.f, 0.f, 0.f);
    for (int c = 0; c < HID; c++) {
        float h = fmaxf(fmaf(ai, sW1r[c], fmaf(xi, sW1o[c], sB1[c])), 0.f);
        const float4* row = &sW2o[c * (HID / 4)];
        #pragma unroll
        for (int j = 0; j < 16; j++) {
            float4 w = row[j];
            acc[j].x = fmaf(h, w.x, acc[j].x);
            acc[j].y = fmaf(h, w.y, acc[j].y);
            acc[j].z = fmaf(h, w.z, acc[j].z);
            acc[j].w = fmaf(h, w.w, acc[j].w);
        }
    }
    {
        float4* out2 = &g_p2[i * (HID / 4)];
        #pragma unroll
        for (int j = 0; j < 16; j++) {
            float4 v = acc[j];
            v.x += sB2[j * 4 + 0];
            v.y += sB2[j * 4 + 1];
            v.z += sB2[j * 4 + 2];
            v.w += sB2[j * 4 + 3];
            out2[j] = v;
        }
    }
}

// ---------------- K7: layer-2 wide aggregation (warp per dst) + fold layer-3 projections
__global__ void __launch_bounds__(256) k_agg2(
    const float* __restrict__ W3_rel, const float* __restrict__ W3_root)
{
    __shared__ float sW3r[HID], sW3o[HID];
    int tid = threadIdx.x;
    if (tid < HID) { sW3r[tid] = W3_rel[tid]; sW3o[tid] = W3_root[tid]; }
    __syncthreads();

    int gwarp = (blockIdx.x * 256 + tid) >> 5;
    int lane = tid & 31;
    if (gwarp >= N_NODES) return;
    int i = gwarp;
    int beg = g_rowptr[i], end = g_rowptr[i + 1];

    const float* g1f = (const float*)g_g1;
    const float* p2f = (const float*)g_p2;

    float acc0 = 0.f, acc1 = 0.f;
    for (int e = beg; e < end; e++) {
        int2 ed = g_edge[e];                       // broadcast load
        float w = __int_as_float(ed.y);
        const float* row = &g1f[(long)ed.x * HID];
        acc0 = fmaf(w, __ldg(&row[lane]),      acc0);
        acc1 = fmaf(w, __ldg(&row[lane + 32]), acc1);
    }
    float h0 = fmaxf(acc0 + p2f[i * HID + lane],      0.f);
    float h1 = fmaxf(acc1 + p2f[i * HID + lane + 32], 0.f);

    float sp = fmaf(h1, sW3r[lane + 32], h0 * sW3r[lane]);
    float tp = fmaf(h1, sW3o[lane + 32], h0 * sW3o[lane]);
    #pragma unroll
    for (int off = 16; off > 0; off >>= 1) {
        sp += __shfl_down_sync(0xFFFFFFFFu, sp, off);
        tp += __shfl_down_sync(0xFFFFFFFFu, tp, off);
    }
    if (lane == 0) { g_s[i] = sp; g_t[i] = tp; }
}

// ---------------- K8: layer-3 scalar aggregation -> out ----------------
__global__ void k_out(const float* __restrict__ b3, float* __restrict__ out) {
    int i = blockIdx.x * blockDim.x + threadIdx.x;
    if (i >= N_NODES) return;
    int beg = g_rowptr[i], end = g_rowptr[i + 1];
    float acc = 0.f;
    for (int e = beg; e < end; e++) {
        int2 ed = g_edge[e];
        acc = fmaf(__int_as_float(ed.y), __ldg(&g_s[ed.x]), acc);
    }
    out[i] = acc + b3[0] + g_t[i];
}

// ---------------- launch ----------------
extern "C" void kernel_launch(void* const* d_in, const int* in_sizes, int n_in,
                              void* d_out, int out_size) {
    const float* x       = (const float*)d_in[0];
    const void*  ei_raw  = d_in[1];
    const float* ew      = (const float*)d_in[2];
    const float* W1_rel  = (const float*)d_in[3];
    const float* b1      = (const float*)d_in[4];
    const float* W1_root = (const float*)d_in[5];
    const float* W2_rel  = (const float*)d_in[6];
    const float* b2      = (const float*)d_in[7];
    const float* W2_root = (const float*)d_in[8];
    const float* W3_rel  = (const float*)d_in[9];
    const float* b3      = (const float*)d_in[10];
    const float* W3_root = (const float*)d_in[11];
    float* out = (float*)d_out;

    const int nb_nodes = (N_NODES + 255) / 256;
    const int nb_edges = (N_EDGES + 255) / 256;

    k_detect<<<1, 32>>>((const unsigned int*)ei_raw);
    k_convert<<<nb_edges, 256>>>(ei_raw);
    k_zero<<<nb_nodes, 256>>>();
    k_hist<<<nb_edges, 256>>>();
    k_scan<<<1, 1024>>>();
    k_scatter<<<nb_edges, 256>>>(ew);
    k_agg1<<<nb_nodes, 256>>>(x);
    k_dense<<<nb_nodes, 256>>>(x, W1_rel, b1, W1_root, W2_rel, b2, W2_root);
    k_agg2<<<(N_NODES * 32 + 255) / 256, 256>>>(W3_rel, W3_root);
    k_out<<<nb_nodes, 256>>>(b3, out);
}

// round 3
// speedup vs baseline: 1.3015x; 1.3015x over previous
#include <cuda_runtime.h>
#include <cuda_fp16.h>
#include <cuda_bf16.h>

#define N_NODES 100000
#define N_EDGES 3200000
#define HID 64
#define SCAN_CHUNK 1024
#define SCAN_BLOCKS ((N_NODES + SCAN_CHUNK - 1) / SCAN_CHUNK)   // 98

// ---------------- scratch (static device globals; no allocation) ----------------
__device__ int          g_is64;
__device__ int          g_cnt[N_NODES];
__device__ int          g_rowptr[N_NODES + 1];
__device__ int          g_cursor[N_NODES];
__device__ int          g_bsum[SCAN_BLOCKS];
__device__ int          g_boff[SCAN_BLOCKS];
__device__ int2         g_edge[N_EDGES];            // {src, bitcast(w)} bucketed by dst
__device__ float        g_a1[N_NODES];              // layer-1 scalar aggregation (atomic)
__device__ unsigned int g_g1h[N_NODES * (HID / 2)]; // h1@W2_rel as half2 (cols 2c,2c+1)
__device__ float4       g_p2[N_NODES * HID / 4];    // b2 + h1@W2_root (fp32)
__device__ float        g_s[N_NODES];               // h2 . W3_rel
__device__ float        g_t[N_NODES];               // h2 . W3_root

// ---------------- K0: detect int64 vs int32 edge_index ----------------
__global__ void k_detect(const unsigned int* __restrict__ w) {
    int t = threadIdx.x;
    unsigned int v = 0;
    for (int i = t; i < 1024; i += 32) v |= w[2 * i + 1];
    #pragma unroll
    for (int off = 16; off > 0; off >>= 1)
        v |= __shfl_down_sync(0xFFFFFFFFu, v, off);
    if (t == 0) g_is64 = (v == 0) ? 1 : 0;
}

// ---------------- K1: zero histogram + a1 ----------------
__global__ void k_zero() {
    int i = blockIdx.x * blockDim.x + threadIdx.x;
    if (i < N_NODES) { g_cnt[i] = 0; g_a1[i] = 0.f; }
}

// ---------------- K2: histogram of dst (reads edge index directly) ----------------
__global__ void k_hist(const void* __restrict__ ei_raw) {
    int e = blockIdx.x * blockDim.x + threadIdx.x;
    if (e >= N_EDGES) return;
    int dst;
    if (g_is64) dst = (int)((const long long*)ei_raw)[N_EDGES + e];
    else        dst = ((const int*)ei_raw)[N_EDGES + e];
    atomicAdd(&g_cnt[dst], 1);
}

// ---------------- K3a: per-block exclusive scan (1024/block) ----------------
__global__ void __launch_bounds__(1024) k_scanA() {
    __shared__ int wsum[32];
    int tid = threadIdx.x;
    int i = blockIdx.x * SCAN_CHUNK + tid;
    int lane = tid & 31, wid = tid >> 5;
    int v = (i < N_NODES) ? g_cnt[i] : 0;
    // warp inclusive scan
    int incl = v;
    #pragma unroll
    for (int off = 1; off < 32; off <<= 1) {
        int n = __shfl_up_sync(0xFFFFFFFFu, incl, off);
        if (lane >= off) incl += n;
    }
    if (lane == 31) wsum[wid] = incl;
    __syncthreads();
    if (wid == 0) {
        int s = wsum[lane];
        int si = s;
        #pragma unroll
        for (int off = 1; off < 32; off <<= 1) {
            int n = __shfl_up_sync(0xFFFFFFFFu, si, off);
            if (lane >= off) si += n;
        }
        wsum[lane] = si - s;           // exclusive warp prefix
        if (lane == 31) g_bsum[blockIdx.x] = si;   // block total
    }
    __syncthreads();
    if (i < N_NODES) g_rowptr[i] = incl - v + wsum[wid];  // block-local exclusive
}

// ---------------- K3b: scan block sums (1 block, 128 threads) ----------------
__global__ void k_scanB() {
    __shared__ int buf[128];
    int t = threadIdx.x;
    int v = (t < SCAN_BLOCKS) ? g_bsum[t] : 0;
    buf[t] = v;
    __syncthreads();
    int acc = v;
    for (int off = 1; off < 128; off <<= 1) {
        int add = (t >= off) ? buf[t - off] : 0;
        __syncthreads();
        acc += add;
        buf[t] = acc;
        __syncthreads();
    }
    if (t < SCAN_BLOCKS) g_boff[t] = acc - v;   // exclusive
}

// ---------------- K3c: add block offsets, init cursor ----------------
__global__ void k_scanC() {
    int i = blockIdx.x * blockDim.x + threadIdx.x;
    if (i < N_NODES) {
        int r = g_rowptr[i] + g_boff[i / SCAN_CHUNK];
        g_rowptr[i] = r;
        g_cursor[i] = r;
    }
    if (i == 0) g_rowptr[N_NODES] = N_EDGES;
}

// ---------------- K4: scatter edges into dst buckets + fused layer-1 agg ----------------
__global__ void k_scatter(const void* __restrict__ ei_raw,
                          const float* __restrict__ ew,
                          const float* __restrict__ x) {
    int e = blockIdx.x * blockDim.x + threadIdx.x;
    if (e >= N_EDGES) return;
    int src, dst;
    if (g_is64) {
        const long long* ei = (const long long*)ei_raw;
        src = (int)ei[e];
        dst = (int)ei[N_EDGES + e];
    } else {
        const int* ei = (const int*)ei_raw;
        src = ei[e];
        dst = ei[N_EDGES + e];
    }
    float w = ew[e];
    int pos = atomicAdd(&g_cursor[dst], 1);
    g_edge[pos] = make_int2(src, __float_as_int(w));
    atomicAdd(&g_a1[dst], w * __ldg(&x[src]));
}

// ---------------- K5: per-node dense: h1 -> g1h (fp16), p2 (fp32) ----------------
__global__ void __launch_bounds__(256) k_dense(
    const float* __restrict__ x,
    const float* __restrict__ W1_rel, const float* __restrict__ b1,
    const float* __restrict__ W1_root,
    const float* __restrict__ W2_rel, const float* __restrict__ b2,
    const float* __restrict__ W2_root)
{
    __shared__ float sW1r[HID], sB1[HID], sW1o[HID], sB2[HID];
    __shared__ float4 sW2r[HID * HID / 4];
    __shared__ float4 sW2o[HID * HID / 4];
    int tid = threadIdx.x;
    if (tid < HID) { sW1r[tid] = W1_rel[tid]; sB1[tid] = b1[tid];
                     sW1o[tid] = W1_root[tid]; sB2[tid] = b2[tid]; }
    for (int k = tid; k < HID * HID / 4; k += 256) {
        sW2r[k] = ((const float4*)W2_rel)[k];
        sW2o[k] = ((const float4*)W2_root)[k];
    }
    __syncthreads();

    int i = blockIdx.x * 256 + tid;
    if (i >= N_NODES) return;
    float xi = x[i];
    float ai = g_a1[i];

    float4 acc[16];
    // ---- pass A: g1 = h1 @ W2_rel  -> fp16x2
    #pragma unroll
    for (int j = 0; j < 16; j++) acc[j] = make_float4(0.f, 0.f, 0.f, 0.f);
    for (int c = 0; c < HID; c++) {
        float h = fmaxf(fmaf(ai, sW1r[c], fmaf(xi, sW1o[c], sB1[c])), 0.f);
        const float4* row = &sW2r[c * (HID / 4)];
        #pragma unroll
        for (int j = 0; j < 16; j++) {
            float4 w = row[j];
            acc[j].x = fmaf(h, w.x, acc[j].x);
            acc[j].y = fmaf(h, w.y, acc[j].y);
            acc[j].z = fmaf(h, w.z, acc[j].z);
            acc[j].w = fmaf(h, w.w, acc[j].w);
        }
    }
    {
        unsigned int* out1 = &g_g1h[i * (HID / 2)];
        #pragma unroll
        for (int j = 0; j < 16; j++) {
            __half2 p0 = __floats2half2_rn(acc[j].x, acc[j].y);
            __half2 p1 = __floats2half2_rn(acc[j].z, acc[j].w);
            out1[j * 2 + 0] = *(unsigned int*)&p0;
            out1[j * 2 + 1] = *(unsigned int*)&p1;
        }
    }
    // ---- pass B: p2 = b2 + h1 @ W2_root (fp32)
    #pragma unroll
    for (int j = 0; j < 16; j++) acc[j] = make_float4(0.f, 0.f, 0.f, 0.f);
    for (int c = 0; c < HID; c++) {
        float h = fmaxf(fmaf(ai, sW1r[c], fmaf(xi, sW1o[c], sB1[c])), 0.f);
        const float4* row = &sW2o[c * (HID / 4)];
        #pragma unroll
        for (int j = 0; j < 16; j++) {
            float4 w = row[j];
            acc[j].x = fmaf(h, w.x, acc[j].x);
            acc[j].y = fmaf(h, w.y, acc[j].y);
            acc[j].z = fmaf(h, w.z, acc[j].z);
            acc[j].w = fmaf(h, w.w, acc[j].w);
        }
    }
    {
        float4* out2 = &g_p2[i * (HID / 4)];
        #pragma unroll
        for (int j = 0; j < 16; j++) {
            float4 v = acc[j];
            v.x += sB2[j * 4 + 0];
            v.y += sB2[j * 4 + 1];
            v.z += sB2[j * 4 + 2];
            v.w += sB2[j * 4 + 3];
            out2[j] = v;
        }
    }
}

// ---------------- K6: layer-2 wide aggregation (warp/dst, fp16 gather) + layer-3 proj ----
__global__ void __launch_bounds__(256) k_agg2(
    const float* __restrict__ W3_rel, const float* __restrict__ W3_root)
{
    __shared__ float sW3r[HID], sW3o[HID];
    int tid = threadIdx.x;
    if (tid < HID) { sW3r[tid] = W3_rel[tid]; sW3o[tid] = W3_root[tid]; }
    __syncthreads();

    int i = (blockIdx.x * 256 + tid) >> 5;
    int lane = tid & 31;
    if (i >= N_NODES) return;
    int beg = g_rowptr[i], end = g_rowptr[i + 1];

    float acc0 = 0.f, acc1 = 0.f;   // cols 2*lane, 2*lane+1
    for (int base = beg; base < end; base += 32) {
        int n = end - base; if (n > 32) n = 32;
        int2 ed = (lane < n) ? g_edge[base + lane] : make_int2(0, 0);
        for (int j = 0; j < n; j++) {
            int   s = __shfl_sync(0xFFFFFFFFu, ed.x, j);
            float w = __int_as_float(__shfl_sync(0xFFFFFFFFu, ed.y, j));
            unsigned int p = __ldg(&g_g1h[s * (HID / 2) + lane]);
            float2 f = __half22float2(*(__half2*)&p);
            acc0 = fmaf(w, f.x, acc0);
            acc1 = fmaf(w, f.y, acc1);
        }
    }
    const float* p2f = (const float*)g_p2;
    float h0 = fmaxf(acc0 + p2f[i * HID + 2 * lane],     0.f);
    float h1 = fmaxf(acc1 + p2f[i * HID + 2 * lane + 1], 0.f);

    float sp = fmaf(h1, sW3r[2 * lane + 1], h0 * sW3r[2 * lane]);
    float tp = fmaf(h1, sW3o[2 * lane + 1], h0 * sW3o[2 * lane]);
    #pragma unroll
    for (int off = 16; off > 0; off >>= 1) {
        sp += __shfl_down_sync(0xFFFFFFFFu, sp, off);
        tp += __shfl_down_sync(0xFFFFFFFFu, tp, off);
    }
    if (lane == 0) { g_s[i] = sp; g_t[i] = tp; }
}

// ---------------- K7: layer-3 scalar aggregation -> out ----------------
__global__ void k_out(const float* __restrict__ b3, float* __restrict__ out) {
    int i = blockIdx.x * blockDim.x + threadIdx.x;
    if (i >= N_NODES) return;
    int beg = g_rowptr[i], end = g_rowptr[i + 1];
    float acc = 0.f;
    for (int e = beg; e < end; e++) {
        int2 ed = g_edge[e];
        acc = fmaf(__int_as_float(ed.y), __ldg(&g_s[ed.x]), acc);
    }
    out[i] = acc + b3[0] + g_t[i];
}

// ---------------- launch ----------------
extern "C" void kernel_launch(void* const* d_in, const int* in_sizes, int n_in,
                              void* d_out, int out_size) {
    const float* x       = (const float*)d_in[0];
    const void*  ei_raw  = d_in[1];
    const float* ew      = (const float*)d_in[2];
    const float* W1_rel  = (const float*)d_in[3];
    const float* b1      = (const float*)d_in[4];
    const float* W1_root = (const float*)d_in[5];
    const float* W2_rel  = (const float*)d_in[6];
    const float* b2      = (const float*)d_in[7];
    const float* W2_root = (const float*)d_in[8];
    const float* W3_rel  = (const float*)d_in[9];
    const float* b3      = (const float*)d_in[10];
    const float* W3_root = (const float*)d_in[11];
    float* out = (float*)d_out;

    const int nb_nodes = (N_NODES + 255) / 256;
    const int nb_edges = (N_EDGES + 255) / 256;

    k_detect<<<1, 32>>>((const unsigned int*)ei_raw);
    k_zero<<<nb_nodes, 256>>>();
    k_hist<<<nb_edges, 256>>>(ei_raw);
    k_scanA<<<SCAN_BLOCKS, 1024>>>();
    k_scanB<<<1, 128>>>();
    k_scanC<<<nb_nodes, 256>>>();
    k_scatter<<<nb_edges, 256>>>(ei_raw, ew, x);
    k_dense<<<nb_nodes, 256>>>(x, W1_rel, b1, W1_root, W2_rel, b2, W2_root);
    k_agg2<<<(N_NODES * 32 + 255) / 256, 256>>>(W3_rel, W3_root);
    k_out<<<nb_nodes, 256>>>(b3, out);
}